// round 13
// baseline (speedup 1.0000x reference)
#include <cuda_runtime.h>
#include <math.h>

#define BD 8
#define HD 48
#define WD 48
#define CD 256
#define NPIX (BD * HD * WD)     // 18432
#define PIXB (HD * WD)          // 2304 pixels per batch
#define PLANE (HD * WD)         // 2304 elems per corr plane
#define SPPB   32               // stats pixels per block (8 warps x 4)
#define SBLKPB (PIXB / SPPB)    // 72 stats blocks per batch
#define NSTATS (BD * SBLKPB)    // 576 stats blocks total (single wave @ 4/SM)

// ---- scratch (device globals; no allocation allowed) ----
__device__ float    g_cvraw[NPIX * 2];
__device__ float    g_partials[NSTATS * 2];  // (sum, sumsq) per stats block
__device__ float    g_stats[BD * 2];         // (mu, inv_std) per batch
__device__ unsigned g_tick[BD];              // stats ticket (self-resetting)

// ================= Kernel 1: MLP + mean + cvraw + fused per-batch reduction =========
// Lane (slot, o) computes the FULL 256-channel dot for (pixel, output o):
// scalar accumulators only -> no register arrays, no spills, no butterflies.
// Weights in TRANSPOSED smem layout wT4[ch4][o]: the 16 lanes (o=0..15) read one
// contiguous 256B block per iteration -> conflict-free. x reads are broadcasts.
__global__ __launch_bounds__(256) void k_stats(
    const float* __restrict__ x,
    const float* __restrict__ map_w, const float* __restrict__ map_b,
    const float* __restrict__ mean_w, const float* __restrict__ mean_b,
    const float* __restrict__ cov_w, const float* __restrict__ cov_b,
    float* __restrict__ out_mean)
{
    __shared__ float4 wT4[64 * 16];   // 16KB: [ch4][o]
    __shared__ float4 sx4[SPPB * 64]; // 32KB: [px][ch4]  (re-used as scratch later)
    const int tid = threadIdx.x;

    {   // transposed weight load (weights are L2-hot; scatter reads are cheap)
        const float4* w4 = (const float4*)map_w;   // [o][ch4]
        for (int i = tid; i < 1024; i += 256) {
            const int o = i & 15, ch4 = i >> 4;
            wT4[ch4 * 16 + o] = w4[o * 64 + ch4];  // STS conflict-free (o consecutive)
        }
        const float4* xg = (const float4*)x + (size_t)blockIdx.x * (SPPB * 64);
        for (int i = tid; i < SPPB * 64; i += 256) sx4[i] = xg[i];
    }
    __syncthreads();

    const int warp = tid >> 5, lane = tid & 31;
    const int batch = blockIdx.x / SBLKPB;
    const int o = lane & 15, slot = lane >> 4;
    const int lp0 = warp * 4 + slot;        // local pixel A (slots 0,1)
    const int lp1 = warp * 4 + 2 + slot;    // local pixel B (slots 2,3)

    // dual accumulators per pixel (even/odd ch4) for FMA-latency ILP
    float a0e = 0.f, a0o = 0.f, a1e = 0.f, a1o = 0.f;
#pragma unroll
    for (int ch4 = 0; ch4 < 64; ch4 += 2) {
        {
            const float4 w  = wT4[ch4 * 16 + o];
            const float4 xa = sx4[lp0 * 64 + ch4];
            const float4 xb = sx4[lp1 * 64 + ch4];
            a0e = fmaf(xa.x, w.x, a0e); a0e = fmaf(xa.y, w.y, a0e);
            a0e = fmaf(xa.z, w.z, a0e); a0e = fmaf(xa.w, w.w, a0e);
            a1e = fmaf(xb.x, w.x, a1e); a1e = fmaf(xb.y, w.y, a1e);
            a1e = fmaf(xb.z, w.z, a1e); a1e = fmaf(xb.w, w.w, a1e);
        }
        {
            const float4 w  = wT4[(ch4 + 1) * 16 + o];
            const float4 xa = sx4[lp0 * 64 + ch4 + 1];
            const float4 xb = sx4[lp1 * 64 + ch4 + 1];
            a0o = fmaf(xa.x, w.x, a0o); a0o = fmaf(xa.y, w.y, a0o);
            a0o = fmaf(xa.z, w.z, a0o); a0o = fmaf(xa.w, w.w, a0o);
            a1o = fmaf(xb.x, w.x, a1o); a1o = fmaf(xb.y, w.y, a1o);
            a1o = fmaf(xb.z, w.z, a1o); a1o = fmaf(xb.w, w.w, a1o);
        }
    }
    const float mb = __ldg(&map_b[o]);
    const float t0 = tanhf(a0e + a0o + mb);
    const float t1 = tanhf(a1e + a1o + mb);

    // all MLP reads of sx4 are complete -> alias scratch over the x tile
    __syncthreads();
    float* scratch = (float*)sx4;
    // layout (float idx): tts[32][17] = 0..543 | s 544..575 | q 576..607 |
    //                     flag @608 | sred 612..683 | sqred 684..755
    scratch[lp0 * 17 + o] = t0;
    scratch[lp1 * 17 + o] = t1;
    __syncthreads();

    // Head MLP: thread t (<32) handles local pixel t (stride-17 reads: conflict-free)
    if (tid < 32) {
        const int pid = blockIdx.x * SPPB + tid;
        float m0 = __ldg(&mean_b[0]), m1 = __ldg(&mean_b[1]);
        float c0 = __ldg(&cov_b[0]),  c1 = __ldg(&cov_b[1]);
        const float* tt = scratch + tid * 17;
#pragma unroll
        for (int k = 0; k < 16; k++) {
            const float t = tt[k];
            m0 = fmaf(t, __ldg(&mean_w[k]),      m0);
            m1 = fmaf(t, __ldg(&mean_w[16 + k]), m1);
            c0 = fmaf(t, __ldg(&cov_w[k]),       c0);
            c1 = fmaf(t, __ldg(&cov_w[16 + k]),  c1);
        }
        const int hw = pid % PIXB;
        out_mean[pid * 2 + 0] = (float)(hw % WD) + m0;
        out_mean[pid * 2 + 1] = (float)(hw / WD) + m1;
        g_cvraw[pid * 2 + 0] = c0;
        g_cvraw[pid * 2 + 1] = c1;
        scratch[544 + tid] = c0 + c1;
        scratch[576 + tid] = c0 * c0 + c1 * c1;
    }
    __syncthreads();

    // block partial (fixed order) + ticket
    if (tid == 0) {
        float s = 0.f, qq = 0.f;
#pragma unroll
        for (int i = 0; i < SPPB; i++) { s += scratch[544 + i]; qq += scratch[576 + i]; }
        g_partials[blockIdx.x * 2 + 0] = s;
        g_partials[blockIdx.x * 2 + 1] = qq;
        __threadfence();
        const unsigned prev = atomicAdd(&g_tick[batch], 1u);
        ((int*)scratch)[608] = (prev == SBLKPB - 1);
    }
    __syncthreads();

    // elected last block of this batch: deterministic fixed-order reduction
    if (((int*)scratch)[608]) {
        __threadfence();
        if (tid < SBLKPB) {
            scratch[612 + tid] = g_partials[(batch * SBLKPB + tid) * 2 + 0];
            scratch[684 + tid] = g_partials[(batch * SBLKPB + tid) * 2 + 1];
        }
        __syncthreads();
        if (tid == 0) {
            float s = 0.f, qq = 0.f;
#pragma unroll
            for (int i = 0; i < SBLKPB; i++) { s += scratch[612 + i]; qq += scratch[684 + i]; }
            const float n = (float)(PIXB * 2);     // 4608
            const float mu = s / n;
            const float var = qq / n - mu * mu + 1e-5f;
            g_stats[batch * 2 + 0] = mu;
            g_stats[batch * 2 + 1] = rsqrtf(var);
            g_tick[batch] = 0;                     // reset for next graph replay
        }
    }
}

// ================= Kernel 2: HBM-bound apply (proven shape: regs 32, occ 84%) =====
__global__ __launch_bounds__(192) void k_apply(
    const float* __restrict__ corr, float* __restrict__ out,
    const float* __restrict__ mean_arr, float* __restrict__ out_det)
{
    const int pid = blockIdx.x;
    const int t = threadIdx.x;
    const float4* __restrict__ src = (const float4*)(corr + (size_t)pid * PLANE);
    float4* __restrict__ dst = (float4*)(out + (size_t)pid * PLANE);

    // issue the 3 streaming DRAM loads first (MLP=3), overlap with param math
    float4 c[3];
#pragma unroll
    for (int it = 0; it < 3; it++) c[it] = __ldcs(src + t + it * 192);

    // per-pixel params (redundant per thread; same-address broadcast, L2-hit)
    const int b = pid / PIXB;
    const float mu = g_stats[b * 2 + 0], istd = g_stats[b * 2 + 1];
    float c0 = (g_cvraw[pid * 2 + 0] - mu) * istd;
    float c1 = (g_cvraw[pid * 2 + 1] - mu) * istd;
    c0 = 5.f / (1.f + __expf(-c0)) + 0.05f;
    c1 = 5.f / (1.f + __expf(-c1)) + 0.05f;
    const float det = c0 * c1;
    if (t == 0) out_det[pid] = det;
    const float mx = __ldg(&mean_arr[pid * 2 + 0]);
    const float my = __ldg(&mean_arr[pid * 2 + 1]);
    const float ax = -0.5f / c0;
    const float ay = -0.5f / c1;
    const float s = rsqrtf(det) * (1.0f / 6.28f);

#pragma unroll
    for (int it = 0; it < 3; it++) {
        const int i = t + it * 192;          // float4 index in plane (0..575)
        const int h2 = i / 12;               // 12 float4s per 48-float row
        const float dy = (float)h2 - my;
        const bool iny = fabsf(dy) <= 6.0f;
        const float qy = ay * dy * dy;
        const float dx0 = (float)((i % 12) * 4) - mx;
        float4 v = c[it];
        {
            const float dx = dx0 + 0.f;
            if (iny && fabsf(dx) <= 6.0f)
                v.x = fmaf(v.x * s, __expf(fmaf(ax, dx * dx, qy)), v.x);
        }
        {
            const float dx = dx0 + 1.f;
            if (iny && fabsf(dx) <= 6.0f)
                v.y = fmaf(v.y * s, __expf(fmaf(ax, dx * dx, qy)), v.y);
        }
        {
            const float dx = dx0 + 2.f;
            if (iny && fabsf(dx) <= 6.0f)
                v.z = fmaf(v.z * s, __expf(fmaf(ax, dx * dx, qy)), v.z);
        }
        {
            const float dx = dx0 + 3.f;
            if (iny && fabsf(dx) <= 6.0f)
                v.w = fmaf(v.w * s, __expf(fmaf(ax, dx * dx, qy)), v.w);
        }
        __stcs(dst + i, v);
    }
}

// ======================================================================
extern "C" void kernel_launch(void* const* d_in, const int* in_sizes, int n_in,
                              void* d_out, int out_size)
{
    const float* x      = (const float*)d_in[0];
    const float* corr   = (const float*)d_in[1];
    const float* map_w  = (const float*)d_in[2];
    const float* map_b  = (const float*)d_in[3];
    const float* mean_w = (const float*)d_in[4];
    const float* mean_b = (const float*)d_in[5];
    const float* cov_w  = (const float*)d_in[6];
    const float* cov_b  = (const float*)d_in[7];

    float* out = (float*)d_out;
    // outputs concatenated flat: corr1 (b,h,w,h,w), mean (b,h,w,2), det (b,h*w)
    float* out_corr1 = out;
    float* out_mean  = out + (size_t)NPIX * PLANE;
    float* out_det   = out_mean + (size_t)NPIX * 2;

    k_stats<<<NSTATS, 256>>>(x, map_w, map_b, mean_w, mean_b, cov_w, cov_b, out_mean);
    k_apply<<<NPIX, 192>>>(corr, out_corr1, out_mean, out_det);
}